// round 11
// baseline (speedup 1.0000x reference)
#include <cuda_runtime.h>
#include <cuda_bf16.h>
#include <math.h>
#include <stdint.h>

#define Nn 10000
#define Ee 160000
#define Dd 512
#define Cc 64

#define KC 16                    // K chunk
#define SROW 24                  // smem row stride in bf16 (48B)
#define TILE_B (128 * SROW * 2)  // 6144 B per tile
#define STAGE_B (4 * TILE_B)     // Ahi,Alo,Bhi,Blo = 24576 B
#define NKC (Dd / KC)            // 32

// -------- scratch --------
__device__ float g_bufA[Nn * Dd];
__device__ float g_bufB[Nn * Dd];
__device__ int   g_deg[Nn];
__device__ float g_dis[Nn];
__device__ int   g_src[Ee];
__device__ int   g_dst[Ee];
__device__ int   g_off[Nn + 1];
__device__ int   g_cur[Nn];
__device__ int   g_eidx[Ee];
__device__ float g_ew[Ee];
__device__ int   g_is64;
__device__ __align__(16) __nv_bfloat16 g_Ahi[Nn * Dd];
__device__ __align__(16) __nv_bfloat16 g_Alo[Nn * Dd];
__device__ __align__(16) __nv_bfloat16 g_W1hi[Dd * Dd];   // [n][k]
__device__ __align__(16) __nv_bfloat16 g_W1lo[Dd * Dd];
__device__ __align__(16) __nv_bfloat16 g_W2hi[Dd * Dd];
__device__ __align__(16) __nv_bfloat16 g_W2lo[Dd * Dd];

#define CP_ASYNC16(smem, gmem, sz) \
    asm volatile("cp.async.cg.shared.global [%0], [%1], 16, %2;" \
                 :: "r"(smem), "l"(gmem), "r"(sz))
#define CP_COMMIT() asm volatile("cp.async.commit_group;" ::: "memory")
#define CP_WAIT(n)  asm volatile("cp.async.wait_group %0;" :: "n"(n) : "memory")

static __device__ __forceinline__ uint32_t smem_u32(const void* p) {
    uint32_t a;
    asm("{ .reg .u64 t; cvta.to.shared.u64 t, %1; cvt.u32.u64 %0, t; }"
        : "=r"(a) : "l"(p));
    return a;
}

// ======== graph preprocessing ========
__global__ void k_detect_init(const int* __restrict__ ei32) {
    int i = blockIdx.x * blockDim.x + threadIdx.x;
    if (i < Nn) { g_deg[i] = 1; g_cur[i] = 0; }
    if (blockIdx.x == 0) {
        __shared__ int nz;
        if (threadIdx.x == 0) nz = 0;
        __syncthreads();
        for (int j = threadIdx.x; j < 1024; j += blockDim.x)
            if (ei32[2 * j + 1] != 0) atomicAdd(&nz, 1);
        __syncthreads();
        if (threadIdx.x == 0) g_is64 = (nz == 0) ? 1 : 0;
    }
}

static __device__ __forceinline__ int clampN(int v) { return min(max(v, 0), Nn - 1); }

__global__ void k_count(const void* __restrict__ ei) {
    int e = blockIdx.x * blockDim.x + threadIdx.x;
    if (e >= Ee) return;
    int s, d;
    if (g_is64) {
        s = (int)((const long long*)ei)[e];
        d = (int)((const long long*)ei)[Ee + e];
    } else {
        s = ((const int*)ei)[e];
        d = ((const int*)ei)[Ee + e];
    }
    s = clampN(s); d = clampN(d);
    g_src[e] = s; g_dst[e] = d;
    if (s != d) atomicAdd(&g_deg[d], 1);
}

// scan of (deg-1) + dis computation, single 1024-thread block
__global__ void k_scan() {
    const int T = 1024, PER = (Nn + T - 1) / T;
    __shared__ int part[T];
    int t = threadIdx.x, base = t * PER, local[PER], sum = 0;
#pragma unroll
    for (int i = 0; i < PER; i++) {
        int idx = base + i;
        int dg = (idx < Nn) ? g_deg[idx] : 1;
        if (idx < Nn) g_dis[idx] = rsqrtf((float)dg);
        local[i] = sum; sum += dg - 1;
    }
    part[t] = sum;
    __syncthreads();
    for (int off = 1; off < T; off <<= 1) {
        int v = (t >= off) ? part[t - off] : 0;
        __syncthreads();
        part[t] += v;
        __syncthreads();
    }
    int prev = (t > 0) ? part[t - 1] : 0;
#pragma unroll
    for (int i = 0; i < PER; i++) {
        int idx = base + i;
        if (idx < Nn) g_off[idx] = prev + local[i];
    }
    if (t == T - 1) g_off[Nn] = part[T - 1];
}

__global__ void k_fill() {
    int e = blockIdx.x * blockDim.x + threadIdx.x;
    if (e >= Ee) return;
    int s = g_src[e], d = g_dst[e];
    if (s == d) return;
    int pos = g_off[d] + atomicAdd(&g_cur[d], 1);
    if (pos >= 0 && pos < Ee) { g_eidx[pos] = s; g_ew[pos] = g_dis[s] * g_dis[d]; }
}

// ======== bf16 hi/lo splits: W1, W2 (transposed) and x, in one launch ========
__global__ void k_split(const float* __restrict__ W1, const float* __restrict__ W2,
                        const float* __restrict__ x) {
    int idx = blockIdx.x * blockDim.x + threadIdx.x;
    if (idx < 2 * Dd * Dd) {
        int layer = idx >= Dd * Dd;
        int li = layer ? idx - Dd * Dd : idx;
        int k = li >> 9, n = li & 511;
        float v = layer ? W2[li] : W1[li];
        __nv_bfloat16 h = __float2bfloat16(v);
        float r = v - __bfloat162float(h);
        if (layer) { g_W2hi[n * Dd + k] = h; g_W2lo[n * Dd + k] = __float2bfloat16(r); }
        else       { g_W1hi[n * Dd + k] = h; g_W1lo[n * Dd + k] = __float2bfloat16(r); }
    } else {
        int li = idx - 2 * Dd * Dd;
        if (li >= Nn * Dd) return;
        float v = x[li];
        __nv_bfloat16 h = __float2bfloat16(v);
        float r = v - __bfloat162float(h);
        g_Ahi[li] = h;
        g_Alo[li] = __float2bfloat16(r);
    }
}

// ======== fused 3-pass bf16 mma GEMM, cp.async double buffer, 2 CTAs/SM =====
static __device__ __forceinline__ void mma16816(
    float& c0, float& c1, float& c2, float& c3,
    uint32_t a0, uint32_t a1, uint32_t a2, uint32_t a3,
    uint32_t b0, uint32_t b1) {
    asm volatile(
        "mma.sync.aligned.m16n8k16.row.col.f32.bf16.bf16.f32 "
        "{%0,%1,%2,%3}, {%4,%5,%6,%7}, {%8,%9}, {%0,%1,%2,%3};"
        : "+f"(c0), "+f"(c1), "+f"(c2), "+f"(c3)
        : "r"(a0), "r"(a1), "r"(a2), "r"(a3), "r"(b0), "r"(b1));
}

extern __shared__ char dynsm[];

__global__ void __launch_bounds__(256, 2) k_gemm_mma(int layer) {
    const __nv_bfloat16* Bhi = layer ? g_W2hi : g_W1hi;
    const __nv_bfloat16* Blo = layer ? g_W2lo : g_W1lo;

    int tid = threadIdx.x;
    int m0 = blockIdx.y * 128;
    int n0 = blockIdx.x * 128;
    int wid = tid >> 5, lane = tid & 31;
    int warp_m = wid >> 2, warp_n = wid & 3;      // 2 x 4
    int q = lane >> 2, tq = lane & 3;

    float c[4][4][4];
#pragma unroll
    for (int mi = 0; mi < 4; mi++)
#pragma unroll
        for (int ni = 0; ni < 4; ni++)
#pragma unroll
            for (int j = 0; j < 4; j++) c[mi][ni][j] = 0.0f;

    // stage one K chunk (KC=16): 4 tiles x 128 rows x 32B = 1024 x 16B
    auto issue = [&](int buf, int kc) {
        char* base = dynsm + buf * STAGE_B;
#pragma unroll
        for (int j = 0; j < 4; j++) {
            int slot = tid + j * 256;             // 0..1023
            int tile = slot >> 8;                 // 0:Ahi 1:Alo 2:Bhi 3:Blo
            int w = slot & 255;
            int r = w >> 1, seg = w & 1;
            const __nv_bfloat16* src;
            int valid = 16;
            if (tile < 2) {
                int gm = m0 + r;
                if (gm >= Nn) { gm = 0; valid = 0; }
                src = (tile == 0 ? g_Ahi : g_Alo) + (size_t)gm * Dd + kc * KC + seg * 8;
            } else {
                src = (tile == 2 ? Bhi : Blo) + (size_t)(n0 + r) * Dd + kc * KC + seg * 8;
            }
            uint32_t dst = smem_u32(base + tile * TILE_B + (r * SROW + seg * 8) * 2);
            CP_ASYNC16(dst, src, valid);
        }
        CP_COMMIT();
    };

    issue(0, 0);

    for (int kc = 0; kc < NKC; kc++) {
        if (kc + 1 < NKC) {
            issue((kc + 1) & 1, kc + 1);
            CP_WAIT(1);
        } else {
            CP_WAIT(0);
        }
        __syncthreads();

        char* base = dynsm + (kc & 1) * STAGE_B;
        const char* pAhi = base;
        const char* pAlo = base + TILE_B;
        const char* pBhi = base + 2 * TILE_B;
        const char* pBlo = base + 3 * TILE_B;

        uint32_t bh[4][2], bl[4][2];
#pragma unroll
        for (int ni = 0; ni < 4; ni++) {
            int n = warp_n * 32 + ni * 8 + q;
            int o0 = (n * SROW + 2 * tq) * 2;
            int o1 = (n * SROW + 2 * tq + 8) * 2;
            bh[ni][0] = *(const uint32_t*)(pBhi + o0);
            bh[ni][1] = *(const uint32_t*)(pBhi + o1);
            bl[ni][0] = *(const uint32_t*)(pBlo + o0);
            bl[ni][1] = *(const uint32_t*)(pBlo + o1);
        }
#pragma unroll
        for (int mi = 0; mi < 4; mi++) {
            int r = warp_m * 64 + mi * 16 + q;
            int o0 = (r * SROW + 2 * tq) * 2;
            int o1 = ((r + 8) * SROW + 2 * tq) * 2;
            int o2 = (r * SROW + 2 * tq + 8) * 2;
            int o3 = ((r + 8) * SROW + 2 * tq + 8) * 2;
            uint32_t ah0 = *(const uint32_t*)(pAhi + o0);
            uint32_t ah1 = *(const uint32_t*)(pAhi + o1);
            uint32_t ah2 = *(const uint32_t*)(pAhi + o2);
            uint32_t ah3 = *(const uint32_t*)(pAhi + o3);
            uint32_t al0 = *(const uint32_t*)(pAlo + o0);
            uint32_t al1 = *(const uint32_t*)(pAlo + o1);
            uint32_t al2 = *(const uint32_t*)(pAlo + o2);
            uint32_t al3 = *(const uint32_t*)(pAlo + o3);
#pragma unroll
            for (int ni = 0; ni < 4; ni++) {
                mma16816(c[mi][ni][0], c[mi][ni][1], c[mi][ni][2], c[mi][ni][3],
                         ah0, ah1, ah2, ah3, bh[ni][0], bh[ni][1]);
                mma16816(c[mi][ni][0], c[mi][ni][1], c[mi][ni][2], c[mi][ni][3],
                         al0, al1, al2, al3, bh[ni][0], bh[ni][1]);
                mma16816(c[mi][ni][0], c[mi][ni][1], c[mi][ni][2], c[mi][ni][3],
                         ah0, ah1, ah2, ah3, bl[ni][0], bl[ni][1]);
            }
        }
        __syncthreads();
    }

#pragma unroll
    for (int mi = 0; mi < 4; mi++) {
#pragma unroll
        for (int ni = 0; ni < 4; ni++) {
            int m = m0 + warp_m * 64 + mi * 16 + q;
            int n = n0 + warp_n * 32 + ni * 8 + 2 * tq;
            if (m < Nn)
                *(float2*)(g_bufA + (size_t)m * Dd + n) =
                    make_float2(c[mi][ni][0], c[mi][ni][1]);
            if (m + 8 < Nn)
                *(float2*)(g_bufA + (size_t)(m + 8) * Dd + n) =
                    make_float2(c[mi][ni][2], c[mi][ni][3]);
        }
    }
}

// ======== gather aggregation + bias (+relu); fp32 bufB or bf16 split ========
__global__ void k_aggr(const float* __restrict__ bias, int relu, int writeSplit) {
    int n = blockIdx.x;
    int t = threadIdx.x;                           // 128 threads x float4
    float ds = g_dis[n];
    float w0 = ds * ds;
    float4 v = ((const float4*)(g_bufA + (size_t)n * Dd))[t];
    float4 acc;
    acc.x = v.x * w0; acc.y = v.y * w0; acc.z = v.z * w0; acc.w = v.w * w0;
    int e0 = g_off[n], e1 = g_off[n + 1];
    for (int e = e0; e < e1; e++) {
        int s = g_eidx[e];
        float w = g_ew[e];
        float4 u = ((const float4*)(g_bufA + (size_t)s * Dd))[t];
        acc.x += u.x * w; acc.y += u.y * w; acc.z += u.z * w; acc.w += u.w * w;
    }
    float4 b = ((const float4*)bias)[t];
    acc.x += b.x; acc.y += b.y; acc.z += b.z; acc.w += b.w;
    if (relu) {
        acc.x = fmaxf(acc.x, 0.0f); acc.y = fmaxf(acc.y, 0.0f);
        acc.z = fmaxf(acc.z, 0.0f); acc.w = fmaxf(acc.w, 0.0f);
    }
    if (writeSplit) {
        size_t o = (size_t)n * Dd + t * 4;
        float vs[4] = {acc.x, acc.y, acc.z, acc.w};
        __nv_bfloat16 hi[4], lo[4];
#pragma unroll
        for (int j = 0; j < 4; j++) {
            hi[j] = __float2bfloat16(vs[j]);
            lo[j] = __float2bfloat16(vs[j] - __bfloat162float(hi[j]));
        }
        *(uint2*)(g_Ahi + o) = *(uint2*)hi;
        *(uint2*)(g_Alo + o) = *(uint2*)lo;
    } else {
        ((float4*)(g_bufB + (size_t)n * Dd))[t] = acc;
    }
}

// ======== classifier + log_softmax: 16 nodes/block, 256 threads ========
__global__ void k_cls(const float* __restrict__ Wc, const float* __restrict__ bc,
                      float* __restrict__ logits, float* __restrict__ logp) {
    __shared__ float xs[16][Dd];
    int t = threadIdx.x;
    int n0 = blockIdx.x * 16;
    int c4 = (t & 15) * 4;
    int g  = t >> 4;

#pragma unroll
    for (int i = 0; i < 8; i++) {
        int slot = t + i * 256;
        int node = slot >> 7, qq = slot & 127;
        ((float4*)xs[node])[qq] = ((const float4*)(g_bufB + (size_t)(n0 + node) * Dd))[qq];
    }
    __syncthreads();

    float a0 = 0.f, a1 = 0.f, a2 = 0.f, a3 = 0.f;
    for (int k = 0; k < Dd; k += 4) {
        float4 xv = *(const float4*)&xs[g][k];
        float4 w0 = *(const float4*)(Wc + (size_t)k * Cc + c4);
        float4 w1 = *(const float4*)(Wc + (size_t)(k + 1) * Cc + c4);
        float4 w2 = *(const float4*)(Wc + (size_t)(k + 2) * Cc + c4);
        float4 w3 = *(const float4*)(Wc + (size_t)(k + 3) * Cc + c4);
        a0 += xv.x * w0.x + xv.y * w1.x + xv.z * w2.x + xv.w * w3.x;
        a1 += xv.x * w0.y + xv.y * w1.y + xv.z * w2.y + xv.w * w3.y;
        a2 += xv.x * w0.z + xv.y * w1.z + xv.z * w2.z + xv.w * w3.z;
        a3 += xv.x * w0.w + xv.y * w1.w + xv.z * w2.w + xv.w * w3.w;
    }
    float4 bv = *(const float4*)(bc + c4);
    a0 += bv.x; a1 += bv.y; a2 += bv.z; a3 += bv.w;

    int n = n0 + g;
    *(float4*)(logits + (size_t)n * Cc + c4) = make_float4(a0, a1, a2, a3);

    float mx = fmaxf(fmaxf(a0, a1), fmaxf(a2, a3));
#pragma unroll
    for (int m = 8; m > 0; m >>= 1)
        mx = fmaxf(mx, __shfl_xor_sync(0xffffffffu, mx, m, 16));
    float es = __expf(a0 - mx) + __expf(a1 - mx) + __expf(a2 - mx) + __expf(a3 - mx);
#pragma unroll
    for (int m = 8; m > 0; m >>= 1)
        es += __shfl_xor_sync(0xffffffffu, es, m, 16);
    float lse = mx + logf(es);
    *(float4*)(logp + (size_t)n * Cc + c4) =
        make_float4(a0 - lse, a1 - lse, a2 - lse, a3 - lse);
}

extern "C" void kernel_launch(void* const* d_in, const int* in_sizes, int n_in,
                              void* d_out, int out_size) {
    const float* x  = 0; const void* ei = 0;
    const float* W1 = 0; const float* b1 = 0;
    const float* W2 = 0; const float* b2 = 0;
    const float* Wc = 0; const float* bc = 0;
    for (int i = 0; i < n_in; i++) {
        int sz = in_sizes[i];
        if (sz == Nn * Dd)      { if (!x)  x  = (const float*)d_in[i]; }
        else if (sz == 2 * Ee)  { if (!ei) ei = d_in[i]; }
        else if (sz == Dd * Dd) { if (!W1) W1 = (const float*)d_in[i];
                                  else if (!W2) W2 = (const float*)d_in[i]; }
        else if (sz == Dd)      { if (!b1) b1 = (const float*)d_in[i];
                                  else if (!b2) b2 = (const float*)d_in[i]; }
        else if (sz == Dd * Cc) { if (!Wc) Wc = (const float*)d_in[i]; }
        else if (sz == Cc)      { if (!bc) bc = (const float*)d_in[i]; }
    }

    float* out    = (float*)d_out;
    float* logits = out;
    float* logp   = out + (out_size - Nn * Cc);

    k_detect_init<<<(Nn + 255) / 256, 256>>>((const int*)ei);
    k_count<<<(Ee + 255) / 256, 256>>>(ei);
    k_scan<<<1, 1024>>>();
    k_fill<<<(Ee + 255) / 256, 256>>>();
    k_split<<<(2 * Dd * Dd + Nn * Dd + 255) / 256, 256>>>(W1, W2, x);

    dim3 gemmGrid(Dd / 128, (Nn + 127) / 128);   // 4 x 79

    // ---- layer 1 ----
    k_gemm_mma<<<gemmGrid, 256, 2 * STAGE_B>>>(0);
    k_aggr<<<Nn, Dd / 4>>>(b1, 1, 1);            // writes bf16 hi/lo for layer 2

    // ---- layer 2 ----
    k_gemm_mma<<<gemmGrid, 256, 2 * STAGE_B>>>(1);
    k_aggr<<<Nn, Dd / 4>>>(b2, 0, 0);            // writes fp32 bufB for classifier

    // ---- classifier + log_softmax ----
    k_cls<<<Nn / 16, 256>>>(Wc, bc, logits, logp);
}

// round 14
// speedup vs baseline: 1.1021x; 1.1021x over previous
#include <cuda_runtime.h>
#include <cuda_bf16.h>
#include <math.h>
#include <stdint.h>

#define Nn 10000
#define Ee 160000
#define Dd 512
#define Cc 64

#define KC 32                    // K chunk
#define SROW 40                  // smem row stride in bf16 (80B)
#define TILE_B (128 * SROW * 2)  // 10240 B per tile
#define STAGE_B (4 * TILE_B)     // Ahi,Alo,Bhi,Blo = 40960 B
#define NKC (Dd / KC)            // 16

// -------- scratch --------
__device__ float g_bufA[Nn * Dd];
__device__ float g_bufB[Nn * Dd];
__device__ int   g_deg[Nn];
__device__ float g_dis[Nn];
__device__ int   g_src[Ee];
__device__ int   g_dst[Ee];
__device__ int   g_off[Nn + 1];
__device__ int   g_cur[Nn];
__device__ int   g_eidx[Ee];
__device__ float g_ew[Ee];
__device__ int   g_is64;
__device__ __align__(16) __nv_bfloat16 g_Ahi[Nn * Dd];
__device__ __align__(16) __nv_bfloat16 g_Alo[Nn * Dd];
__device__ __align__(16) __nv_bfloat16 g_W1hi[Dd * Dd];   // [n][k]
__device__ __align__(16) __nv_bfloat16 g_W1lo[Dd * Dd];
__device__ __align__(16) __nv_bfloat16 g_W2hi[Dd * Dd];
__device__ __align__(16) __nv_bfloat16 g_W2lo[Dd * Dd];

#define CP_ASYNC16(smem, gmem, sz) \
    asm volatile("cp.async.cg.shared.global [%0], [%1], 16, %2;" \
                 :: "r"(smem), "l"(gmem), "r"(sz))
#define CP_COMMIT() asm volatile("cp.async.commit_group;" ::: "memory")
#define CP_WAIT(n)  asm volatile("cp.async.wait_group %0;" :: "n"(n) : "memory")

static __device__ __forceinline__ uint32_t smem_u32(const void* p) {
    uint32_t a;
    asm("{ .reg .u64 t; cvta.to.shared.u64 t, %1; cvt.u32.u64 %0, t; }"
        : "=r"(a) : "l"(p));
    return a;
}

// ======== graph preprocessing ========
__global__ void k_detect_init(const int* __restrict__ ei32) {
    int i = blockIdx.x * blockDim.x + threadIdx.x;
    if (i < Nn) { g_deg[i] = 1; g_cur[i] = 0; }
    if (blockIdx.x == 0) {
        __shared__ int nz;
        if (threadIdx.x == 0) nz = 0;
        __syncthreads();
        for (int j = threadIdx.x; j < 1024; j += blockDim.x)
            if (ei32[2 * j + 1] != 0) atomicAdd(&nz, 1);
        __syncthreads();
        if (threadIdx.x == 0) g_is64 = (nz == 0) ? 1 : 0;
    }
}

static __device__ __forceinline__ int clampN(int v) { return min(max(v, 0), Nn - 1); }

__global__ void k_count(const void* __restrict__ ei) {
    int e = blockIdx.x * blockDim.x + threadIdx.x;
    if (e >= Ee) return;
    int s, d;
    if (g_is64) {
        s = (int)((const long long*)ei)[e];
        d = (int)((const long long*)ei)[Ee + e];
    } else {
        s = ((const int*)ei)[e];
        d = ((const int*)ei)[Ee + e];
    }
    s = clampN(s); d = clampN(d);
    g_src[e] = s; g_dst[e] = d;
    if (s != d) atomicAdd(&g_deg[d], 1);
}

// scan of (deg-1) + dis computation, single 1024-thread block
__global__ void k_scan() {
    const int T = 1024, PER = (Nn + T - 1) / T;
    __shared__ int part[T];
    int t = threadIdx.x, base = t * PER, local[PER], sum = 0;
#pragma unroll
    for (int i = 0; i < PER; i++) {
        int idx = base + i;
        int dg = (idx < Nn) ? g_deg[idx] : 1;
        if (idx < Nn) g_dis[idx] = rsqrtf((float)dg);
        local[i] = sum; sum += dg - 1;
    }
    part[t] = sum;
    __syncthreads();
    for (int off = 1; off < T; off <<= 1) {
        int v = (t >= off) ? part[t - off] : 0;
        __syncthreads();
        part[t] += v;
        __syncthreads();
    }
    int prev = (t > 0) ? part[t - 1] : 0;
#pragma unroll
    for (int i = 0; i < PER; i++) {
        int idx = base + i;
        if (idx < Nn) g_off[idx] = prev + local[i];
    }
    if (t == T - 1) g_off[Nn] = part[T - 1];
}

__global__ void k_fill() {
    int e = blockIdx.x * blockDim.x + threadIdx.x;
    if (e >= Ee) return;
    int s = g_src[e], d = g_dst[e];
    if (s == d) return;
    int pos = g_off[d] + atomicAdd(&g_cur[d], 1);
    if (pos >= 0 && pos < Ee) { g_eidx[pos] = s; g_ew[pos] = g_dis[s] * g_dis[d]; }
}

// ======== bf16 hi/lo splits: W1, W2 (transposed) and x, in one launch ========
__global__ void k_split(const float* __restrict__ W1, const float* __restrict__ W2,
                        const float* __restrict__ x) {
    int idx = blockIdx.x * blockDim.x + threadIdx.x;
    if (idx < 2 * Dd * Dd) {
        int layer = idx >= Dd * Dd;
        int li = layer ? idx - Dd * Dd : idx;
        int k = li >> 9, n = li & 511;
        float v = layer ? W2[li] : W1[li];
        __nv_bfloat16 h = __float2bfloat16(v);
        float r = v - __bfloat162float(h);
        if (layer) { g_W2hi[n * Dd + k] = h; g_W2lo[n * Dd + k] = __float2bfloat16(r); }
        else       { g_W1hi[n * Dd + k] = h; g_W1lo[n * Dd + k] = __float2bfloat16(r); }
    } else {
        int li = idx - 2 * Dd * Dd;
        if (li >= Nn * Dd) return;
        float v = x[li];
        __nv_bfloat16 h = __float2bfloat16(v);
        float r = v - __bfloat162float(h);
        g_Ahi[li] = h;
        g_Alo[li] = __float2bfloat16(r);
    }
}

// ======== fused 3-pass bf16 mma GEMM, cp.async double buffer, 2 CTAs/SM =====
static __device__ __forceinline__ void mma16816(
    float& c0, float& c1, float& c2, float& c3,
    uint32_t a0, uint32_t a1, uint32_t a2, uint32_t a3,
    uint32_t b0, uint32_t b1) {
    asm volatile(
        "mma.sync.aligned.m16n8k16.row.col.f32.bf16.bf16.f32 "
        "{%0,%1,%2,%3}, {%4,%5,%6,%7}, {%8,%9}, {%0,%1,%2,%3};"
        : "+f"(c0), "+f"(c1), "+f"(c2), "+f"(c3)
        : "r"(a0), "r"(a1), "r"(a2), "r"(a3), "r"(b0), "r"(b1));
}

extern __shared__ char dynsm[];

__global__ void __launch_bounds__(256, 2) k_gemm_mma(int layer) {
    const __nv_bfloat16* Bhi = layer ? g_W2hi : g_W1hi;
    const __nv_bfloat16* Blo = layer ? g_W2lo : g_W1lo;

    int tid = threadIdx.x;
    int m0 = blockIdx.y * 128;
    int n0 = blockIdx.x * 128;
    int wid = tid >> 5, lane = tid & 31;
    int warp_m = wid >> 2, warp_n = wid & 3;      // 2 x 4
    int q = lane >> 2, tq = lane & 3;

    float c[4][4][4];
#pragma unroll
    for (int mi = 0; mi < 4; mi++)
#pragma unroll
        for (int ni = 0; ni < 4; ni++)
#pragma unroll
            for (int j = 0; j < 4; j++) c[mi][ni][j] = 0.0f;

    // stage one K chunk (KC=32): 4 tiles x 128 rows x 64B = 2048 x 16B
    auto issue = [&](int buf, int kc) {
        char* base = dynsm + buf * STAGE_B;
#pragma unroll
        for (int j = 0; j < 8; j++) {
            int slot = tid + j * 256;             // 0..2047
            int tile = slot >> 9;                 // 0:Ahi 1:Alo 2:Bhi 3:Blo
            int w = slot & 511;
            int r = w >> 2, seg = w & 3;
            const __nv_bfloat16* src;
            int valid = 16;
            if (tile < 2) {
                int gm = m0 + r;
                if (gm >= Nn) { gm = 0; valid = 0; }
                src = (tile == 0 ? g_Ahi : g_Alo) + (size_t)gm * Dd + kc * KC + seg * 8;
            } else {
                src = (tile == 2 ? Bhi : Blo) + (size_t)(n0 + r) * Dd + kc * KC + seg * 8;
            }
            uint32_t dst = smem_u32(base + tile * TILE_B + (r * SROW + seg * 8) * 2);
            CP_ASYNC16(dst, src, valid);
        }
        CP_COMMIT();
    };

    issue(0, 0);

    for (int kc = 0; kc < NKC; kc++) {
        if (kc + 1 < NKC) {
            issue((kc + 1) & 1, kc + 1);
            CP_WAIT(1);
        } else {
            CP_WAIT(0);
        }
        __syncthreads();

        char* base = dynsm + (kc & 1) * STAGE_B;
        const char* pAhi = base;
        const char* pAlo = base + TILE_B;
        const char* pBhi = base + 2 * TILE_B;
        const char* pBlo = base + 3 * TILE_B;

#pragma unroll
        for (int ks = 0; ks < KC; ks += 16) {
            uint32_t bh[4][2], bl[4][2];
#pragma unroll
            for (int ni = 0; ni < 4; ni++) {
                int n = warp_n * 32 + ni * 8 + q;
                int o0 = (n * SROW + ks + 2 * tq) * 2;
                int o1 = (n * SROW + ks + 2 * tq + 8) * 2;
                bh[ni][0] = *(const uint32_t*)(pBhi + o0);
                bh[ni][1] = *(const uint32_t*)(pBhi + o1);
                bl[ni][0] = *(const uint32_t*)(pBlo + o0);
                bl[ni][1] = *(const uint32_t*)(pBlo + o1);
            }
#pragma unroll
            for (int mi = 0; mi < 4; mi++) {
                int r = warp_m * 64 + mi * 16 + q;
                int o0 = (r * SROW + ks + 2 * tq) * 2;
                int o1 = ((r + 8) * SROW + ks + 2 * tq) * 2;
                int o2 = (r * SROW + ks + 2 * tq + 8) * 2;
                int o3 = ((r + 8) * SROW + ks + 2 * tq + 8) * 2;
                uint32_t ah0 = *(const uint32_t*)(pAhi + o0);
                uint32_t ah1 = *(const uint32_t*)(pAhi + o1);
                uint32_t ah2 = *(const uint32_t*)(pAhi + o2);
                uint32_t ah3 = *(const uint32_t*)(pAhi + o3);
                uint32_t al0 = *(const uint32_t*)(pAlo + o0);
                uint32_t al1 = *(const uint32_t*)(pAlo + o1);
                uint32_t al2 = *(const uint32_t*)(pAlo + o2);
                uint32_t al3 = *(const uint32_t*)(pAlo + o3);
#pragma unroll
                for (int ni = 0; ni < 4; ni++) {
                    mma16816(c[mi][ni][0], c[mi][ni][1], c[mi][ni][2], c[mi][ni][3],
                             ah0, ah1, ah2, ah3, bh[ni][0], bh[ni][1]);
                    mma16816(c[mi][ni][0], c[mi][ni][1], c[mi][ni][2], c[mi][ni][3],
                             al0, al1, al2, al3, bh[ni][0], bh[ni][1]);
                    mma16816(c[mi][ni][0], c[mi][ni][1], c[mi][ni][2], c[mi][ni][3],
                             ah0, ah1, ah2, ah3, bl[ni][0], bl[ni][1]);
                }
            }
        }
        __syncthreads();
    }

#pragma unroll
    for (int mi = 0; mi < 4; mi++) {
#pragma unroll
        for (int ni = 0; ni < 4; ni++) {
            int m = m0 + warp_m * 64 + mi * 16 + q;
            int n = n0 + warp_n * 32 + ni * 8 + 2 * tq;
            if (m < Nn)
                *(float2*)(g_bufA + (size_t)m * Dd + n) =
                    make_float2(c[mi][ni][0], c[mi][ni][1]);
            if (m + 8 < Nn)
                *(float2*)(g_bufA + (size_t)(m + 8) * Dd + n) =
                    make_float2(c[mi][ni][2], c[mi][ni][3]);
        }
    }
}

// ======== gather aggregation + bias (+relu); fp32 bufB or bf16 split ========
__global__ void k_aggr(const float* __restrict__ bias, int relu, int writeSplit) {
    int n = blockIdx.x;
    int t = threadIdx.x;                           // 128 threads x float4
    float ds = g_dis[n];
    float w0 = ds * ds;
    float4 v = ((const float4*)(g_bufA + (size_t)n * Dd))[t];
    float4 acc;
    acc.x = v.x * w0; acc.y = v.y * w0; acc.z = v.z * w0; acc.w = v.w * w0;
    int e0 = g_off[n], e1 = g_off[n + 1];
    for (int e = e0; e < e1; e++) {
        int s = g_eidx[e];
        float w = g_ew[e];
        float4 u = ((const float4*)(g_bufA + (size_t)s * Dd))[t];
        acc.x += u.x * w; acc.y += u.y * w; acc.z += u.z * w; acc.w += u.w * w;
    }
    float4 b = ((const float4*)bias)[t];
    acc.x += b.x; acc.y += b.y; acc.z += b.z; acc.w += b.w;
    if (relu) {
        acc.x = fmaxf(acc.x, 0.0f); acc.y = fmaxf(acc.y, 0.0f);
        acc.z = fmaxf(acc.z, 0.0f); acc.w = fmaxf(acc.w, 0.0f);
    }
    if (writeSplit) {
        size_t o = (size_t)n * Dd + t * 4;
        float vs[4] = {acc.x, acc.y, acc.z, acc.w};
        __nv_bfloat16 hi[4], lo[4];
#pragma unroll
        for (int j = 0; j < 4; j++) {
            hi[j] = __float2bfloat16(vs[j]);
            lo[j] = __float2bfloat16(vs[j] - __bfloat162float(hi[j]));
        }
        *(uint2*)(g_Ahi + o) = *(uint2*)hi;
        *(uint2*)(g_Alo + o) = *(uint2*)lo;
    } else {
        ((float4*)(g_bufB + (size_t)n * Dd))[t] = acc;
    }
}

// ======== classifier + log_softmax: 16 nodes/block, 256 threads ========
__global__ void k_cls(const float* __restrict__ Wc, const float* __restrict__ bc,
                      float* __restrict__ logits, float* __restrict__ logp) {
    __shared__ float xs[16][Dd];
    int t = threadIdx.x;
    int n0 = blockIdx.x * 16;
    int c4 = (t & 15) * 4;
    int g  = t >> 4;

#pragma unroll
    for (int i = 0; i < 8; i++) {
        int slot = t + i * 256;
        int node = slot >> 7, qq = slot & 127;
        ((float4*)xs[node])[qq] = ((const float4*)(g_bufB + (size_t)(n0 + node) * Dd))[qq];
    }
    __syncthreads();

    float a0 = 0.f, a1 = 0.f, a2 = 0.f, a3 = 0.f;
    for (int k = 0; k < Dd; k += 4) {
        float4 xv = *(const float4*)&xs[g][k];
        float4 w0 = *(const float4*)(Wc + (size_t)k * Cc + c4);
        float4 w1 = *(const float4*)(Wc + (size_t)(k + 1) * Cc + c4);
        float4 w2 = *(const float4*)(Wc + (size_t)(k + 2) * Cc + c4);
        float4 w3 = *(const float4*)(Wc + (size_t)(k + 3) * Cc + c4);
        a0 += xv.x * w0.x + xv.y * w1.x + xv.z * w2.x + xv.w * w3.x;
        a1 += xv.x * w0.y + xv.y * w1.y + xv.z * w2.y + xv.w * w3.y;
        a2 += xv.x * w0.z + xv.y * w1.z + xv.z * w2.z + xv.w * w3.z;
        a3 += xv.x * w0.w + xv.y * w1.w + xv.z * w2.w + xv.w * w3.w;
    }
    float4 bv = *(const float4*)(bc + c4);
    a0 += bv.x; a1 += bv.y; a2 += bv.z; a3 += bv.w;

    int n = n0 + g;
    *(float4*)(logits + (size_t)n * Cc + c4) = make_float4(a0, a1, a2, a3);

    float mx = fmaxf(fmaxf(a0, a1), fmaxf(a2, a3));
#pragma unroll
    for (int m = 8; m > 0; m >>= 1)
        mx = fmaxf(mx, __shfl_xor_sync(0xffffffffu, mx, m, 16));
    float es = __expf(a0 - mx) + __expf(a1 - mx) + __expf(a2 - mx) + __expf(a3 - mx);
#pragma unroll
    for (int m = 8; m > 0; m >>= 1)
        es += __shfl_xor_sync(0xffffffffu, es, m, 16);
    float lse = mx + logf(es);
    *(float4*)(logp + (size_t)n * Cc + c4) =
        make_float4(a0 - lse, a1 - lse, a2 - lse, a3 - lse);
}

extern "C" void kernel_launch(void* const* d_in, const int* in_sizes, int n_in,
                              void* d_out, int out_size) {
    const float* x  = 0; const void* ei = 0;
    const float* W1 = 0; const float* b1 = 0;
    const float* W2 = 0; const float* b2 = 0;
    const float* Wc = 0; const float* bc = 0;
    for (int i = 0; i < n_in; i++) {
        int sz = in_sizes[i];
        if (sz == Nn * Dd)      { if (!x)  x  = (const float*)d_in[i]; }
        else if (sz == 2 * Ee)  { if (!ei) ei = d_in[i]; }
        else if (sz == Dd * Dd) { if (!W1) W1 = (const float*)d_in[i];
                                  else if (!W2) W2 = (const float*)d_in[i]; }
        else if (sz == Dd)      { if (!b1) b1 = (const float*)d_in[i];
                                  else if (!b2) b2 = (const float*)d_in[i]; }
        else if (sz == Dd * Cc) { if (!Wc) Wc = (const float*)d_in[i]; }
        else if (sz == Cc)      { if (!bc) bc = (const float*)d_in[i]; }
    }

    float* out    = (float*)d_out;
    float* logits = out;
    float* logp   = out + (out_size - Nn * Cc);

    static int smemSet = 0;
    if (!smemSet) {
        cudaFuncSetAttribute(k_gemm_mma,
                             cudaFuncAttributeMaxDynamicSharedMemorySize, 2 * STAGE_B);
        smemSet = 1;
    }

    k_detect_init<<<(Nn + 255) / 256, 256>>>((const int*)ei);
    k_count<<<(Ee + 255) / 256, 256>>>(ei);
    k_scan<<<1, 1024>>>();
    k_fill<<<(Ee + 255) / 256, 256>>>();
    k_split<<<(2 * Dd * Dd + Nn * Dd + 255) / 256, 256>>>(W1, W2, x);

    dim3 gemmGrid(Dd / 128, (Nn + 127) / 128);   // 4 x 79

    // ---- layer 1 ----
    k_gemm_mma<<<gemmGrid, 256, 2 * STAGE_B>>>(0);
    k_aggr<<<Nn, Dd / 4>>>(b1, 1, 1);            // writes bf16 hi/lo for layer 2

    // ---- layer 2 ----
    k_gemm_mma<<<gemmGrid, 256, 2 * STAGE_B>>>(1);
    k_aggr<<<Nn, Dd / 4>>>(b2, 0, 0);            // writes fp32 bufB for classifier

    // ---- classifier + log_softmax ----
    k_cls<<<Nn / 16, 256>>>(Wc, bc, logits, logp);
}

// round 15
// speedup vs baseline: 1.2029x; 1.0915x over previous
#include <cuda_runtime.h>
#include <cuda_bf16.h>
#include <math.h>
#include <stdint.h>

#define Nn 10000
#define Ee 160000
#define Dd 512
#define Cc 64

#define KC 32                     // K chunk
#define SROW 40                   // smem row stride in bf16 (80B)
#define MT 160                    // M tile
#define TILE_A_B (MT * SROW * 2)  // 12800 B
#define TILE_B_B (128 * SROW * 2) // 10240 B
#define STAGE_B (2 * TILE_A_B + 2 * TILE_B_B)  // 46080 B
#define NKC (Dd / KC)             // 16

// -------- scratch --------
__device__ float g_bufA[Nn * Dd];
__device__ float g_bufB[Nn * Dd];
__device__ int   g_deg[Nn];
__device__ float g_dis[Nn];
__device__ int   g_src[Ee];
__device__ int   g_dst[Ee];
__device__ int   g_off[Nn + 1];
__device__ int   g_cur[Nn];
__device__ int   g_eidx[Ee];
__device__ float g_ew[Ee];
__device__ __align__(16) __nv_bfloat16 g_Ahi[Nn * Dd];
__device__ __align__(16) __nv_bfloat16 g_Alo[Nn * Dd];
__device__ __align__(16) __nv_bfloat16 g_W1hi[Dd * Dd];   // [n][k]
__device__ __align__(16) __nv_bfloat16 g_W1lo[Dd * Dd];
__device__ __align__(16) __nv_bfloat16 g_W2hi[Dd * Dd];
__device__ __align__(16) __nv_bfloat16 g_W2lo[Dd * Dd];

#define CP_ASYNC16(smem, gmem, sz) \
    asm volatile("cp.async.cg.shared.global [%0], [%1], 16, %2;" \
                 :: "r"(smem), "l"(gmem), "r"(sz))
#define CP_COMMIT() asm volatile("cp.async.commit_group;" ::: "memory")
#define CP_WAIT(n)  asm volatile("cp.async.wait_group %0;" :: "n"(n) : "memory")

static __device__ __forceinline__ uint32_t smem_u32(const void* p) {
    uint32_t a;
    asm("{ .reg .u64 t; cvta.to.shared.u64 t, %1; cvt.u32.u64 %0, t; }"
        : "=r"(a) : "l"(p));
    return a;
}

// ======== graph preprocessing ========
__global__ void k_init() {
    int i = blockIdx.x * blockDim.x + threadIdx.x;
    if (i < Nn) { g_deg[i] = 1; g_cur[i] = 0; }
}

static __device__ __forceinline__ int clampN(int v) { return min(max(v, 0), Nn - 1); }

// decode (either dtype; every block derives the same is64 from first 1024 pairs)
__global__ void k_count(const void* __restrict__ ei) {
    __shared__ int nz;
    if (threadIdx.x == 0) nz = 0;
    __syncthreads();
    const int* e32 = (const int*)ei;
    for (int j = threadIdx.x; j < 1024; j += blockDim.x)
        if (e32[2 * j + 1] != 0) atomicAdd(&nz, 1);
    __syncthreads();
    int is64 = (nz == 0);

    int e = blockIdx.x * blockDim.x + threadIdx.x;
    if (e >= Ee) return;
    int s, d;
    if (is64) {
        s = (int)((const long long*)ei)[e];
        d = (int)((const long long*)ei)[Ee + e];
    } else {
        s = e32[e];
        d = e32[Ee + e];
    }
    s = clampN(s); d = clampN(d);
    g_src[e] = s; g_dst[e] = d;
    if (s != d) atomicAdd(&g_deg[d], 1);
}

// scan of (deg-1) + dis computation, single 1024-thread block
__global__ void k_scan() {
    const int T = 1024, PER = (Nn + T - 1) / T;
    __shared__ int part[T];
    int t = threadIdx.x, base = t * PER, local[PER], sum = 0;
#pragma unroll
    for (int i = 0; i < PER; i++) {
        int idx = base + i;
        int dg = (idx < Nn) ? g_deg[idx] : 1;
        if (idx < Nn) g_dis[idx] = rsqrtf((float)dg);
        local[i] = sum; sum += dg - 1;
    }
    part[t] = sum;
    __syncthreads();
    for (int off = 1; off < T; off <<= 1) {
        int v = (t >= off) ? part[t - off] : 0;
        __syncthreads();
        part[t] += v;
        __syncthreads();
    }
    int prev = (t > 0) ? part[t - 1] : 0;
#pragma unroll
    for (int i = 0; i < PER; i++) {
        int idx = base + i;
        if (idx < Nn) g_off[idx] = prev + local[i];
    }
    if (t == T - 1) g_off[Nn] = part[T - 1];
}

__global__ void k_fill() {
    int e = blockIdx.x * blockDim.x + threadIdx.x;
    if (e >= Ee) return;
    int s = g_src[e], d = g_dst[e];
    if (s == d) return;
    int pos = g_off[d] + atomicAdd(&g_cur[d], 1);
    if (pos >= 0 && pos < Ee) { g_eidx[pos] = s; g_ew[pos] = g_dis[s] * g_dis[d]; }
}

// ======== bf16 hi/lo splits: W1, W2 (transposed) and x, one launch ========
__global__ void k_split(const float* __restrict__ W1, const float* __restrict__ W2,
                        const float* __restrict__ x) {
    int idx = blockIdx.x * blockDim.x + threadIdx.x;
    if (idx < 2 * Dd * Dd) {
        int layer = idx >= Dd * Dd;
        int li = layer ? idx - Dd * Dd : idx;
        int k = li >> 9, n = li & 511;
        float v = layer ? W2[li] : W1[li];
        __nv_bfloat16 h = __float2bfloat16(v);
        float r = v - __bfloat162float(h);
        if (layer) { g_W2hi[n * Dd + k] = h; g_W2lo[n * Dd + k] = __float2bfloat16(r); }
        else       { g_W1hi[n * Dd + k] = h; g_W1lo[n * Dd + k] = __float2bfloat16(r); }
    } else {
        int li = idx - 2 * Dd * Dd;
        if (li >= Nn * Dd) return;
        float v = x[li];
        __nv_bfloat16 h = __float2bfloat16(v);
        float r = v - __bfloat162float(h);
        g_Ahi[li] = h;
        g_Alo[li] = __float2bfloat16(r);
    }
}

// ======== fused 3-pass bf16 mma GEMM, 160x128 tile, 1 full wave ========
static __device__ __forceinline__ void mma16816(
    float& c0, float& c1, float& c2, float& c3,
    uint32_t a0, uint32_t a1, uint32_t a2, uint32_t a3,
    uint32_t b0, uint32_t b1) {
    asm volatile(
        "mma.sync.aligned.m16n8k16.row.col.f32.bf16.bf16.f32 "
        "{%0,%1,%2,%3}, {%4,%5,%6,%7}, {%8,%9}, {%0,%1,%2,%3};"
        : "+f"(c0), "+f"(c1), "+f"(c2), "+f"(c3)
        : "r"(a0), "r"(a1), "r"(a2), "r"(a3), "r"(b0), "r"(b1));
}

extern __shared__ char dynsm[];

__global__ void __launch_bounds__(256, 2) k_gemm_mma(int layer) {
    const __nv_bfloat16* Bhi = layer ? g_W2hi : g_W1hi;
    const __nv_bfloat16* Blo = layer ? g_W2lo : g_W1lo;

    int tid = threadIdx.x;
    int m0 = blockIdx.y * MT;
    int n0 = blockIdx.x * 128;
    int wid = tid >> 5, lane = tid & 31;
    int warp_m = wid >> 2, warp_n = wid & 3;      // 2 x 4; warp tile 80 x 32
    int q = lane >> 2, tq = lane & 3;

    float c[5][4][4];
#pragma unroll
    for (int mi = 0; mi < 5; mi++)
#pragma unroll
        for (int ni = 0; ni < 4; ni++)
#pragma unroll
            for (int j = 0; j < 4; j++) c[mi][ni][j] = 0.0f;

    // stage one K chunk: Ahi(640) Alo(640) Bhi(512) Blo(512) 16B slots = 2304
    auto issue = [&](int buf, int kc) {
        char* base = dynsm + buf * STAGE_B;
#pragma unroll
        for (int j = 0; j < 9; j++) {
            int slot = tid + j * 256;             // 0..2303
            const __nv_bfloat16* src;
            uint32_t dst;
            int valid = 16;
            if (slot < 1280) {                    // A tiles
                int tile = slot >= 640;           // 0:Ahi 1:Alo
                int w = tile ? slot - 640 : slot;
                int r = w >> 2, seg = w & 3;
                int gm = m0 + r;
                if (gm >= Nn) { gm = 0; valid = 0; }
                src = (tile ? g_Alo : g_Ahi) + (size_t)gm * Dd + kc * KC + seg * 8;
                dst = smem_u32(base + tile * TILE_A_B + (r * SROW + seg * 8) * 2);
            } else {                              // B tiles
                int w = slot - 1280;
                int tile = w >= 512;              // 0:Bhi 1:Blo
                if (tile) w -= 512;
                int r = w >> 2, seg = w & 3;
                src = (tile ? Blo : Bhi) + (size_t)(n0 + r) * Dd + kc * KC + seg * 8;
                dst = smem_u32(base + 2 * TILE_A_B + tile * TILE_B_B +
                               (r * SROW + seg * 8) * 2);
            }
            CP_ASYNC16(dst, src, valid);
        }
        CP_COMMIT();
    };

    issue(0, 0);

    for (int kc = 0; kc < NKC; kc++) {
        if (kc + 1 < NKC) {
            issue((kc + 1) & 1, kc + 1);
            CP_WAIT(1);
        } else {
            CP_WAIT(0);
        }
        __syncthreads();

        char* base = dynsm + (kc & 1) * STAGE_B;
        const char* pAhi = base;
        const char* pAlo = base + TILE_A_B;
        const char* pBhi = base + 2 * TILE_A_B;
        const char* pBlo = base + 2 * TILE_A_B + TILE_B_B;

#pragma unroll
        for (int ks = 0; ks < KC; ks += 16) {
            uint32_t bh[4][2], bl[4][2];
#pragma unroll
            for (int ni = 0; ni < 4; ni++) {
                int n = warp_n * 32 + ni * 8 + q;
                int o0 = (n * SROW + ks + 2 * tq) * 2;
                int o1 = (n * SROW + ks + 2 * tq + 8) * 2;
                bh[ni][0] = *(const uint32_t*)(pBhi + o0);
                bh[ni][1] = *(const uint32_t*)(pBhi + o1);
                bl[ni][0] = *(const uint32_t*)(pBlo + o0);
                bl[ni][1] = *(const uint32_t*)(pBlo + o1);
            }
#pragma unroll
            for (int mi = 0; mi < 5; mi++) {
                int r = warp_m * 80 + mi * 16 + q;
                int o0 = (r * SROW + ks + 2 * tq) * 2;
                int o1 = ((r + 8) * SROW + ks + 2 * tq) * 2;
                int o2 = (r * SROW + ks + 2 * tq + 8) * 2;
                int o3 = ((r + 8) * SROW + ks + 2 * tq + 8) * 2;
                uint32_t ah0 = *(const uint32_t*)(pAhi + o0);
                uint32_t ah1 = *(const uint32_t*)(pAhi + o1);
                uint32_t ah2 = *(const uint32_t*)(pAhi + o2);
                uint32_t ah3 = *(const uint32_t*)(pAhi + o3);
                uint32_t al0 = *(const uint32_t*)(pAlo + o0);
                uint32_t al1 = *(const uint32_t*)(pAlo + o1);
                uint32_t al2 = *(const uint32_t*)(pAlo + o2);
                uint32_t al3 = *(const uint32_t*)(pAlo + o3);
#pragma unroll
                for (int ni = 0; ni < 4; ni++) {
                    mma16816(c[mi][ni][0], c[mi][ni][1], c[mi][ni][2], c[mi][ni][3],
                             ah0, ah1, ah2, ah3, bh[ni][0], bh[ni][1]);
                    mma16816(c[mi][ni][0], c[mi][ni][1], c[mi][ni][2], c[mi][ni][3],
                             al0, al1, al2, al3, bh[ni][0], bh[ni][1]);
                    mma16816(c[mi][ni][0], c[mi][ni][1], c[mi][ni][2], c[mi][ni][3],
                             ah0, ah1, ah2, ah3, bl[ni][0], bl[ni][1]);
                }
            }
        }
        __syncthreads();
    }

#pragma unroll
    for (int mi = 0; mi < 5; mi++) {
#pragma unroll
        for (int ni = 0; ni < 4; ni++) {
            int m = m0 + warp_m * 80 + mi * 16 + q;
            int n = n0 + warp_n * 32 + ni * 8 + 2 * tq;
            if (m < Nn)
                *(float2*)(g_bufA + (size_t)m * Dd + n) =
                    make_float2(c[mi][ni][0], c[mi][ni][1]);
            if (m + 8 < Nn)
                *(float2*)(g_bufA + (size_t)(m + 8) * Dd + n) =
                    make_float2(c[mi][ni][2], c[mi][ni][3]);
        }
    }
}

// ======== gather aggregation + bias (+relu); fp32 bufB or bf16 split ========
__global__ void k_aggr(const float* __restrict__ bias, int relu, int writeSplit) {
    int n = blockIdx.x;
    int t = threadIdx.x;                           // 128 threads x float4
    float ds = g_dis[n];
    float w0 = ds * ds;
    float4 v = ((const float4*)(g_bufA + (size_t)n * Dd))[t];
    float4 acc;
    acc.x = v.x * w0; acc.y = v.y * w0; acc.z = v.z * w0; acc.w = v.w * w0;
    int e0 = g_off[n], e1 = g_off[n + 1];
    for (int e = e0; e < e1; e++) {
        int s = g_eidx[e];
        float w = g_ew[e];
        float4 u = ((const float4*)(g_bufA + (size_t)s * Dd))[t];
        acc.x += u.x * w; acc.y += u.y * w; acc.z += u.z * w; acc.w += u.w * w;
    }
    float4 b = ((const float4*)bias)[t];
    acc.x += b.x; acc.y += b.y; acc.z += b.z; acc.w += b.w;
    if (relu) {
        acc.x = fmaxf(acc.x, 0.0f); acc.y = fmaxf(acc.y, 0.0f);
        acc.z = fmaxf(acc.z, 0.0f); acc.w = fmaxf(acc.w, 0.0f);
    }
    if (writeSplit) {
        size_t o = (size_t)n * Dd + t * 4;
        float vs[4] = {acc.x, acc.y, acc.z, acc.w};
        __nv_bfloat16 hi[4], lo[4];
#pragma unroll
        for (int j = 0; j < 4; j++) {
            hi[j] = __float2bfloat16(vs[j]);
            lo[j] = __float2bfloat16(vs[j] - __bfloat162float(hi[j]));
        }
        *(uint2*)(g_Ahi + o) = *(uint2*)hi;
        *(uint2*)(g_Alo + o) = *(uint2*)lo;
    } else {
        ((float4*)(g_bufB + (size_t)n * Dd))[t] = acc;
    }
}

// ======== classifier + log_softmax: 16 nodes/block, 256 threads ========
__global__ void k_cls(const float* __restrict__ Wc, const float* __restrict__ bc,
                      float* __restrict__ logits, float* __restrict__ logp) {
    __shared__ float xs[16][Dd];
    int t = threadIdx.x;
    int n0 = blockIdx.x * 16;
    int c4 = (t & 15) * 4;
    int g  = t >> 4;

#pragma unroll
    for (int i = 0; i < 8; i++) {
        int slot = t + i * 256;
        int node = slot >> 7, qq = slot & 127;
        ((float4*)xs[node])[qq] = ((const float4*)(g_bufB + (size_t)(n0 + node) * Dd))[qq];
    }
    __syncthreads();

    float a0 = 0.f, a1 = 0.f, a2 = 0.f, a3 = 0.f;
    for (int k = 0; k < Dd; k += 4) {
        float4 xv = *(const float4*)&xs[g][k];
        float4 w0 = *(const float4*)(Wc + (size_t)k * Cc + c4);
        float4 w1 = *(const float4*)(Wc + (size_t)(k + 1) * Cc + c4);
        float4 w2 = *(const float4*)(Wc + (size_t)(k + 2) * Cc + c4);
        float4 w3 = *(const float4*)(Wc + (size_t)(k + 3) * Cc + c4);
        a0 += xv.x * w0.x + xv.y * w1.x + xv.z * w2.x + xv.w * w3.x;
        a1 += xv.x * w0.y + xv.y * w1.y + xv.z * w2.y + xv.w * w3.y;
        a2 += xv.x * w0.z + xv.y * w1.z + xv.z * w2.z + xv.w * w3.z;
        a3 += xv.x * w0.w + xv.y * w1.w + xv.z * w2.w + xv.w * w3.w;
    }
    float4 bv = *(const float4*)(bc + c4);
    a0 += bv.x; a1 += bv.y; a2 += bv.z; a3 += bv.w;

    int n = n0 + g;
    *(float4*)(logits + (size_t)n * Cc + c4) = make_float4(a0, a1, a2, a3);

    float mx = fmaxf(fmaxf(a0, a1), fmaxf(a2, a3));
#pragma unroll
    for (int m = 8; m > 0; m >>= 1)
        mx = fmaxf(mx, __shfl_xor_sync(0xffffffffu, mx, m, 16));
    float es = __expf(a0 - mx) + __expf(a1 - mx) + __expf(a2 - mx) + __expf(a3 - mx);
#pragma unroll
    for (int m = 8; m > 0; m >>= 1)
        es += __shfl_xor_sync(0xffffffffu, es, m, 16);
    float lse = mx + logf(es);
    *(float4*)(logp + (size_t)n * Cc + c4) =
        make_float4(a0 - lse, a1 - lse, a2 - lse, a3 - lse);
}

extern "C" void kernel_launch(void* const* d_in, const int* in_sizes, int n_in,
                              void* d_out, int out_size) {
    const float* x  = 0; const void* ei = 0;
    const float* W1 = 0; const float* b1 = 0;
    const float* W2 = 0; const float* b2 = 0;
    const float* Wc = 0; const float* bc = 0;
    for (int i = 0; i < n_in; i++) {
        int sz = in_sizes[i];
        if (sz == Nn * Dd)      { if (!x)  x  = (const float*)d_in[i]; }
        else if (sz == 2 * Ee)  { if (!ei) ei = d_in[i]; }
        else if (sz == Dd * Dd) { if (!W1) W1 = (const float*)d_in[i];
                                  else if (!W2) W2 = (const float*)d_in[i]; }
        else if (sz == Dd)      { if (!b1) b1 = (const float*)d_in[i];
                                  else if (!b2) b2 = (const float*)d_in[i]; }
        else if (sz == Dd * Cc) { if (!Wc) Wc = (const float*)d_in[i]; }
        else if (sz == Cc)      { if (!bc) bc = (const float*)d_in[i]; }
    }

    float* out    = (float*)d_out;
    float* logits = out;
    float* logp   = out + (out_size - Nn * Cc);

    static int smemSet = 0;
    if (!smemSet) {
        cudaFuncSetAttribute(k_gemm_mma,
                             cudaFuncAttributeMaxDynamicSharedMemorySize, 2 * STAGE_B);
        smemSet = 1;
    }

    k_init<<<(Nn + 255) / 256, 256>>>();
    k_count<<<(Ee + 255) / 256, 256>>>(ei);
    k_scan<<<1, 1024>>>();
    k_fill<<<(Ee + 255) / 256, 256>>>();
    k_split<<<(2 * Dd * Dd + Nn * Dd + 255) / 256, 256>>>(W1, W2, x);

    dim3 gemmGrid(Dd / 128, (Nn + MT - 1) / MT);   // 4 x 63 = 252 CTAs

    // ---- layer 1 ----
    k_gemm_mma<<<gemmGrid, 256, 2 * STAGE_B>>>(0);
    k_aggr<<<Nn, Dd / 4>>>(b1, 1, 1);            // writes bf16 hi/lo for layer 2

    // ---- layer 2 ----
    k_gemm_mma<<<gemmGrid, 256, 2 * STAGE_B>>>(1);
    k_aggr<<<Nn, Dd / 4>>>(b2, 0, 0);            // writes fp32 bufB for classifier

    // ---- classifier + log_softmax ----
    k_cls<<<Nn / 16, 256>>>(Wc, bc, logits, logp);
}

// round 17
// speedup vs baseline: 1.2988x; 1.0797x over previous
#include <cuda_runtime.h>
#include <cuda_bf16.h>
#include <math.h>
#include <stdint.h>

#define Nn 10000
#define Ee 160000
#define Dd 512
#define Cc 64

#define KC 32                     // K chunk
#define SROW 40                   // smem row stride in bf16 (80B)
#define MT 160                    // M tile
#define TILE_A_B (MT * SROW * 2)  // 12800 B
#define TILE_B_B (128 * SROW * 2) // 10240 B
#define STAGE_B (2 * TILE_A_B + 2 * TILE_B_B)  // 46080 B
#define NKC (Dd / KC)             // 16

// -------- scratch --------
__device__ float g_bufA[Nn * Dd];
__device__ float g_bufB[Nn * Dd];
__device__ int   g_deg[Nn];
__device__ float g_dis[Nn];
__device__ int   g_src[Ee];
__device__ int   g_dst[Ee];
__device__ int   g_off[Nn + 1];
__device__ int   g_cur[Nn];
__device__ int   g_eidx[Ee];
__device__ float g_ew[Ee];
__device__ __align__(16) __nv_bfloat16 g_Ahi[Nn * Dd];
__device__ __align__(16) __nv_bfloat16 g_Alo[Nn * Dd];
__device__ __align__(16) __nv_bfloat16 g_W1hi[Dd * Dd];   // [n][k]
__device__ __align__(16) __nv_bfloat16 g_W1lo[Dd * Dd];
__device__ __align__(16) __nv_bfloat16 g_W2hi[Dd * Dd];
__device__ __align__(16) __nv_bfloat16 g_W2lo[Dd * Dd];

#define CP_ASYNC16(smem, gmem, sz) \
    asm volatile("cp.async.cg.shared.global [%0], [%1], 16, %2;" \
                 :: "r"(smem), "l"(gmem), "r"(sz))
#define CP_COMMIT() asm volatile("cp.async.commit_group;" ::: "memory")
#define CP_WAIT(n)  asm volatile("cp.async.wait_group %0;" :: "n"(n) : "memory")

static __device__ __forceinline__ uint32_t smem_u32(const void* p) {
    uint32_t a;
    asm("{ .reg .u64 t; cvta.to.shared.u64 t, %1; cvt.u32.u64 %0, t; }"
        : "=r"(a) : "l"(p));
    return a;
}

// ======== graph preprocessing ========
__global__ void k_init() {
    int i = blockIdx.x * blockDim.x + threadIdx.x;
    if (i < Nn) { g_deg[i] = 1; g_cur[i] = 0; }
}

static __device__ __forceinline__ int clampN(int v) { return min(max(v, 0), Nn - 1); }

// decode (either dtype; every block derives the same is64 from first 1024 pairs)
__global__ void k_count(const void* __restrict__ ei) {
    __shared__ int nz;
    if (threadIdx.x == 0) nz = 0;
    __syncthreads();
    const int* e32 = (const int*)ei;
    for (int j = threadIdx.x; j < 1024; j += blockDim.x)
        if (e32[2 * j + 1] != 0) atomicAdd(&nz, 1);
    __syncthreads();
    int is64 = (nz == 0);

    int e = blockIdx.x * blockDim.x + threadIdx.x;
    if (e >= Ee) return;
    int s, d;
    if (is64) {
        s = (int)((const long long*)ei)[e];
        d = (int)((const long long*)ei)[Ee + e];
    } else {
        s = e32[e];
        d = e32[Ee + e];
    }
    s = clampN(s); d = clampN(d);
    g_src[e] = s; g_dst[e] = d;
    if (s != d) atomicAdd(&g_deg[d], 1);
}

// scan of (deg-1) + dis computation, single 1024-thread block
__global__ void k_scan() {
    const int T = 1024, PER = (Nn + T - 1) / T;
    __shared__ int part[T];
    int t = threadIdx.x, base = t * PER, local[PER], sum = 0;
#pragma unroll
    for (int i = 0; i < PER; i++) {
        int idx = base + i;
        int dg = (idx < Nn) ? g_deg[idx] : 1;
        if (idx < Nn) g_dis[idx] = rsqrtf((float)dg);
        local[i] = sum; sum += dg - 1;
    }
    part[t] = sum;
    __syncthreads();
    for (int off = 1; off < T; off <<= 1) {
        int v = (t >= off) ? part[t - off] : 0;
        __syncthreads();
        part[t] += v;
        __syncthreads();
    }
    int prev = (t > 0) ? part[t - 1] : 0;
#pragma unroll
    for (int i = 0; i < PER; i++) {
        int idx = base + i;
        if (idx < Nn) g_off[idx] = prev + local[i];
    }
    if (t == T - 1) g_off[Nn] = part[T - 1];
}

__global__ void k_fill() {
    int e = blockIdx.x * blockDim.x + threadIdx.x;
    if (e >= Ee) return;
    int s = g_src[e], d = g_dst[e];
    if (s == d) return;
    int pos = g_off[d] + atomicAdd(&g_cur[d], 1);
    if (pos >= 0 && pos < Ee) { g_eidx[pos] = s; g_ew[pos] = g_dis[s] * g_dis[d]; }
}

// ======== bf16 hi/lo splits: W1, W2 (transposed) and x, one launch ========
__global__ void k_split(const float* __restrict__ W1, const float* __restrict__ W2,
                        const float* __restrict__ x) {
    int idx = blockIdx.x * blockDim.x + threadIdx.x;
    if (idx < 2 * Dd * Dd) {
        int layer = idx >= Dd * Dd;
        int li = layer ? idx - Dd * Dd : idx;
        int k = li >> 9, n = li & 511;
        float v = layer ? W2[li] : W1[li];
        __nv_bfloat16 h = __float2bfloat16(v);
        float r = v - __bfloat162float(h);
        if (layer) { g_W2hi[n * Dd + k] = h; g_W2lo[n * Dd + k] = __float2bfloat16(r); }
        else       { g_W1hi[n * Dd + k] = h; g_W1lo[n * Dd + k] = __float2bfloat16(r); }
    } else {
        int li = idx - 2 * Dd * Dd;
        if (li >= Nn * Dd) return;
        float v = x[li];
        __nv_bfloat16 h = __float2bfloat16(v);
        float r = v - __bfloat162float(h);
        g_Ahi[li] = h;
        g_Alo[li] = __float2bfloat16(r);
    }
}

// ======== fused 3-pass bf16 mma GEMM, 160x128 tile, 1 full wave ========
static __device__ __forceinline__ void mma16816(
    float& c0, float& c1, float& c2, float& c3,
    uint32_t a0, uint32_t a1, uint32_t a2, uint32_t a3,
    uint32_t b0, uint32_t b1) {
    asm volatile(
        "mma.sync.aligned.m16n8k16.row.col.f32.bf16.bf16.f32 "
        "{%0,%1,%2,%3}, {%4,%5,%6,%7}, {%8,%9}, {%0,%1,%2,%3};"
        : "+f"(c0), "+f"(c1), "+f"(c2), "+f"(c3)
        : "r"(a0), "r"(a1), "r"(a2), "r"(a3), "r"(b0), "r"(b1));
}

extern __shared__ char dynsm[];

__global__ void __launch_bounds__(256, 2) k_gemm_mma(int layer) {
    const __nv_bfloat16* Bhi = layer ? g_W2hi : g_W1hi;
    const __nv_bfloat16* Blo = layer ? g_W2lo : g_W1lo;

    int tid = threadIdx.x;
    int m0 = blockIdx.y * MT;
    int n0 = blockIdx.x * 128;
    int wid = tid >> 5, lane = tid & 31;
    int warp_m = wid >> 2, warp_n = wid & 3;      // 2 x 4; warp tile 80 x 32
    int q = lane >> 2, tq = lane & 3;

    float c[5][4][4];
#pragma unroll
    for (int mi = 0; mi < 5; mi++)
#pragma unroll
        for (int ni = 0; ni < 4; ni++)
#pragma unroll
            for (int j = 0; j < 4; j++) c[mi][ni][j] = 0.0f;

    // stage one K chunk: Ahi(640) Alo(640) Bhi(512) Blo(512) 16B slots = 2304
    auto issue = [&](int buf, int kc) {
        char* base = dynsm + buf * STAGE_B;
#pragma unroll
        for (int j = 0; j < 9; j++) {
            int slot = tid + j * 256;             // 0..2303
            const __nv_bfloat16* src;
            uint32_t dst;
            int valid = 16;
            if (slot < 1280) {                    // A tiles
                int tile = slot >= 640;           // 0:Ahi 1:Alo
                int w = tile ? slot - 640 : slot;
                int r = w >> 2, seg = w & 3;
                int gm = m0 + r;
                if (gm >= Nn) { gm = 0; valid = 0; }
                src = (tile ? g_Alo : g_Ahi) + (size_t)gm * Dd + kc * KC + seg * 8;
                dst = smem_u32(base + tile * TILE_A_B + (r * SROW + seg * 8) * 2);
            } else {                              // B tiles
                int w = slot - 1280;
                int tile = w >= 512;              // 0:Bhi 1:Blo
                if (tile) w -= 512;
                int r = w >> 2, seg = w & 3;
                src = (tile ? Blo : Bhi) + (size_t)(n0 + r) * Dd + kc * KC + seg * 8;
                dst = smem_u32(base + 2 * TILE_A_B + tile * TILE_B_B +
                               (r * SROW + seg * 8) * 2);
            }
            CP_ASYNC16(dst, src, valid);
        }
        CP_COMMIT();
    };

    issue(0, 0);

    for (int kc = 0; kc < NKC; kc++) {
        if (kc + 1 < NKC) {
            issue((kc + 1) & 1, kc + 1);
            CP_WAIT(1);
        } else {
            CP_WAIT(0);
        }
        __syncthreads();

        char* base = dynsm + (kc & 1) * STAGE_B;
        const char* pAhi = base;
        const char* pAlo = base + TILE_A_B;
        const char* pBhi = base + 2 * TILE_A_B;
        const char* pBlo = base + 2 * TILE_A_B + TILE_B_B;

#pragma unroll
        for (int ks = 0; ks < KC; ks += 16) {
            uint32_t bh[4][2], bl[4][2];
#pragma unroll
            for (int ni = 0; ni < 4; ni++) {
                int n = warp_n * 32 + ni * 8 + q;
                int o0 = (n * SROW + ks + 2 * tq) * 2;
                int o1 = (n * SROW + ks + 2 * tq + 8) * 2;
                bh[ni][0] = *(const uint32_t*)(pBhi + o0);
                bh[ni][1] = *(const uint32_t*)(pBhi + o1);
                bl[ni][0] = *(const uint32_t*)(pBlo + o0);
                bl[ni][1] = *(const uint32_t*)(pBlo + o1);
            }
#pragma unroll
            for (int mi = 0; mi < 5; mi++) {
                int r = warp_m * 80 + mi * 16 + q;
                int o0 = (r * SROW + ks + 2 * tq) * 2;
                int o1 = ((r + 8) * SROW + ks + 2 * tq) * 2;
                int o2 = (r * SROW + ks + 2 * tq + 8) * 2;
                int o3 = ((r + 8) * SROW + ks + 2 * tq + 8) * 2;
                uint32_t ah0 = *(const uint32_t*)(pAhi + o0);
                uint32_t ah1 = *(const uint32_t*)(pAhi + o1);
                uint32_t ah2 = *(const uint32_t*)(pAhi + o2);
                uint32_t ah3 = *(const uint32_t*)(pAhi + o3);
                uint32_t al0 = *(const uint32_t*)(pAlo + o0);
                uint32_t al1 = *(const uint32_t*)(pAlo + o1);
                uint32_t al2 = *(const uint32_t*)(pAlo + o2);
                uint32_t al3 = *(const uint32_t*)(pAlo + o3);
#pragma unroll
                for (int ni = 0; ni < 4; ni++) {
                    mma16816(c[mi][ni][0], c[mi][ni][1], c[mi][ni][2], c[mi][ni][3],
                             ah0, ah1, ah2, ah3, bh[ni][0], bh[ni][1]);
                    mma16816(c[mi][ni][0], c[mi][ni][1], c[mi][ni][2], c[mi][ni][3],
                             al0, al1, al2, al3, bh[ni][0], bh[ni][1]);
                    mma16816(c[mi][ni][0], c[mi][ni][1], c[mi][ni][2], c[mi][ni][3],
                             ah0, ah1, ah2, ah3, bl[ni][0], bl[ni][1]);
                }
            }
        }
        __syncthreads();
    }

#pragma unroll
    for (int mi = 0; mi < 5; mi++) {
#pragma unroll
        for (int ni = 0; ni < 4; ni++) {
            int m = m0 + warp_m * 80 + mi * 16 + q;
            int n = n0 + warp_n * 32 + ni * 8 + 2 * tq;
            if (m < Nn)
                *(float2*)(g_bufA + (size_t)m * Dd + n) =
                    make_float2(c[mi][ni][0], c[mi][ni][1]);
            if (m + 8 < Nn)
                *(float2*)(g_bufA + (size_t)(m + 8) * Dd + n) =
                    make_float2(c[mi][ni][2], c[mi][ni][3]);
        }
    }
}

// ======== gather aggregation + bias (+relu); fp32 bufB or bf16 split ========
__global__ void k_aggr(const float* __restrict__ bias, int relu, int writeSplit) {
    int n = blockIdx.x;
    int t = threadIdx.x;                           // 128 threads x float4
    float ds = g_dis[n];
    float w0 = ds * ds;
    float4 v = ((const float4*)(g_bufA + (size_t)n * Dd))[t];
    float4 acc;
    acc.x = v.x * w0; acc.y = v.y * w0; acc.z = v.z * w0; acc.w = v.w * w0;
    int e0 = g_off[n], e1 = g_off[n + 1];
    for (int e = e0; e < e1; e++) {
        int s = g_eidx[e];
        float w = g_ew[e];
        float4 u = ((const float4*)(g_bufA + (size_t)s * Dd))[t];
        acc.x += u.x * w; acc.y += u.y * w; acc.z += u.z * w; acc.w += u.w * w;
    }
    float4 b = ((const float4*)bias)[t];
    acc.x += b.x; acc.y += b.y; acc.z += b.z; acc.w += b.w;
    if (relu) {
        acc.x = fmaxf(acc.x, 0.0f); acc.y = fmaxf(acc.y, 0.0f);
        acc.z = fmaxf(acc.z, 0.0f); acc.w = fmaxf(acc.w, 0.0f);
    }
    if (writeSplit) {
        size_t o = (size_t)n * Dd + t * 4;
        float vs[4] = {acc.x, acc.y, acc.z, acc.w};
        __nv_bfloat16 hi[4], lo[4];
#pragma unroll
        for (int j = 0; j < 4; j++) {
            hi[j] = __float2bfloat16(vs[j]);
            lo[j] = __float2bfloat16(vs[j] - __bfloat162float(hi[j]));
        }
        *(uint2*)(g_Ahi + o) = *(uint2*)hi;
        *(uint2*)(g_Alo + o) = *(uint2*)lo;
    } else {
        ((float4*)(g_bufB + (size_t)n * Dd))[t] = acc;
    }
}

// ======== classifier + log_softmax: 16 nodes/block, 256 threads ========
__global__ void k_cls(const float* __restrict__ Wc, const float* __restrict__ bc,
                      float* __restrict__ logits, float* __restrict__ logp) {
    __shared__ float xs[16][Dd];
    int t = threadIdx.x;
    int n0 = blockIdx.x * 16;
    int c4 = (t & 15) * 4;
    int g  = t >> 4;

#pragma unroll
    for (int i = 0; i < 8; i++) {
        int slot = t + i * 256;
        int node = slot >> 7, qq = slot & 127;
        ((float4*)xs[node])[qq] = ((const float4*)(g_bufB + (size_t)(n0 + node) * Dd))[qq];
    }
    __syncthreads();

    float a0 = 0.f, a1 = 0.f, a2 = 0.f, a3 = 0.f;
    for (int k = 0; k < Dd; k += 4) {
        float4 xv = *(const float4*)&xs[g][k];
        float4 w0 = *(const float4*)(Wc + (size_t)k * Cc + c4);
        float4 w1 = *(const float4*)(Wc + (size_t)(k + 1) * Cc + c4);
        float4 w2 = *(const float4*)(Wc + (size_t)(k + 2) * Cc + c4);
        float4 w3 = *(const float4*)(Wc + (size_t)(k + 3) * Cc + c4);
        a0 += xv.x * w0.x + xv.y * w1.x + xv.z * w2.x + xv.w * w3.x;
        a1 += xv.x * w0.y + xv.y * w1.y + xv.z * w2.y + xv.w * w3.y;
        a2 += xv.x * w0.z + xv.y * w1.z + xv.z * w2.z + xv.w * w3.z;
        a3 += xv.x * w0.w + xv.y * w1.w + xv.z * w2.w + xv.w * w3.w;
    }
    float4 bv = *(const float4*)(bc + c4);
    a0 += bv.x; a1 += bv.y; a2 += bv.z; a3 += bv.w;

    int n = n0 + g;
    *(float4*)(logits + (size_t)n * Cc + c4) = make_float4(a0, a1, a2, a3);

    float mx = fmaxf(fmaxf(a0, a1), fmaxf(a2, a3));
#pragma unroll
    for (int m = 8; m > 0; m >>= 1)
        mx = fmaxf(mx, __shfl_xor_sync(0xffffffffu, mx, m, 16));
    float es = __expf(a0 - mx) + __expf(a1 - mx) + __expf(a2 - mx) + __expf(a3 - mx);
#pragma unroll
    for (int m = 8; m > 0; m >>= 1)
        es += __shfl_xor_sync(0xffffffffu, es, m, 16);
    float lse = mx + logf(es);
    *(float4*)(logp + (size_t)n * Cc + c4) =
        make_float4(a0 - lse, a1 - lse, a2 - lse, a3 - lse);
}

extern "C" void kernel_launch(void* const* d_in, const int* in_sizes, int n_in,
                              void* d_out, int out_size) {
    const float* x  = 0; const void* ei = 0;
    const float* W1 = 0; const float* b1 = 0;
    const float* W2 = 0; const float* b2 = 0;
    const float* Wc = 0; const float* bc = 0;
    for (int i = 0; i < n_in; i++) {
        int sz = in_sizes[i];
        if (sz == Nn * Dd)      { if (!x)  x  = (const float*)d_in[i]; }
        else if (sz == 2 * Ee)  { if (!ei) ei = d_in[i]; }
        else if (sz == Dd * Dd) { if (!W1) W1 = (const float*)d_in[i];
                                  else if (!W2) W2 = (const float*)d_in[i]; }
        else if (sz == Dd)      { if (!b1) b1 = (const float*)d_in[i];
                                  else if (!b2) b2 = (const float*)d_in[i]; }
        else if (sz == Dd * Cc) { if (!Wc) Wc = (const float*)d_in[i]; }
        else if (sz == Cc)      { if (!bc) bc = (const float*)d_in[i]; }
    }

    float* out    = (float*)d_out;
    float* logits = out;
    float* logp   = out + (out_size - Nn * Cc);

    static int inited = 0;
    static cudaStream_t s2;
    static cudaEvent_t evFork, evJoin;
    if (!inited) {
        cudaFuncSetAttribute(k_gemm_mma,
                             cudaFuncAttributeMaxDynamicSharedMemorySize, 2 * STAGE_B);
        cudaStreamCreateWithFlags(&s2, cudaStreamNonBlocking);
        cudaEventCreateWithFlags(&evFork, cudaEventDisableTiming);
        cudaEventCreateWithFlags(&evJoin, cudaEventDisableTiming);
        inited = 1;
    }

    // fork: graph preprocessing on side stream, overlapped with split+gemm1
    cudaEventRecord(evFork, 0);
    cudaStreamWaitEvent(s2, evFork, 0);
    k_init<<<(Nn + 255) / 256, 256, 0, s2>>>();
    k_count<<<(Ee + 255) / 256, 256, 0, s2>>>(ei);
    k_scan<<<1, 1024, 0, s2>>>();
    k_fill<<<(Ee + 255) / 256, 256, 0, s2>>>();
    cudaEventRecord(evJoin, s2);

    // main stream: splits + layer-1 GEMM (independent of graph preproc)
    k_split<<<(2 * Dd * Dd + Nn * Dd + 255) / 256, 256>>>(W1, W2, x);

    dim3 gemmGrid(Dd / 128, (Nn + MT - 1) / MT);   // 4 x 63 = 252 CTAs
    k_gemm_mma<<<gemmGrid, 256, 2 * STAGE_B>>>(0);

    // join: aggregation needs CSR + gemm1 output
    cudaStreamWaitEvent(0, evJoin, 0);
    k_aggr<<<Nn, Dd / 4>>>(b1, 1, 1);            // writes bf16 hi/lo for layer 2

    // ---- layer 2 ----
    k_gemm_mma<<<gemmGrid, 256, 2 * STAGE_B>>>(1);
    k_aggr<<<Nn, Dd / 4>>>(b2, 0, 0);            // writes fp32 bufB for classifier

    // ---- classifier + log_softmax ----
    k_cls<<<Nn / 16, 256>>>(Wc, bc, logits, logp);
}